// round 15
// baseline (speedup 1.0000x reference)
#include <cuda_runtime.h>
#include <cuda_bf16.h>
#include <cuda_fp16.h>
#include <cstdint>

#define NUM_USERS 100000
#define NUM_ITEMS 50000
#define N_NODES   150000
#define EMB_DIM   64
#define TEXT_DIM  384
#define N64 (N_NODES * EMB_DIM)
#define MAX_EDGES 5000000
#define SCAN_BLOCKS 147           // 147 * 1024 = 150528 >= N_NODES

// fp16 interleaved buffers: per node 16 uint4; uint4 q of a node =
//   (id pair 2q, tx pair 2q, id pair 2q+1, tx pair 2q+1)
__device__ unsigned g_b0[N_NODES * 64];
__device__ unsigned g_b1[N_NODES * 64];
__device__ unsigned g_b2[N_NODES * 64];

// CSR machinery
__device__ int  g_cnt[N_NODES];
__device__ int  g_ofs[N_NODES + 1];
__device__ int  g_cur[N_NODES];
__device__ int  g_bsum[SCAN_BLOCKS];
__device__ int  g_boff[SCAN_BLOCKS];
__device__ int2 g_edges[MAX_EDGES];   // (col, val bits), row-sorted

static __device__ __forceinline__ unsigned pack_h2(float a, float b) {
    __half2 h = __floats2half2_rn(a, b);
    return *reinterpret_cast<unsigned*>(&h);
}
static __device__ __forceinline__ float2 unpack_h2(unsigned w) {
    return __half22float2(*reinterpret_cast<__half2*>(&w));
}

// ---------------------------------------------------------------------------
// CSR build (side stream): memset zero, int4 histogram, 3-phase scan, scatter
// ---------------------------------------------------------------------------
__global__ void hist_kernel(const int* __restrict__ erow, int n_edges) {
    int base = (blockIdx.x * blockDim.x + threadIdx.x) * 4;
    if (base + 3 < n_edges) {
        int4 r = *(const int4*)(erow + base);
        atomicAdd(&g_cnt[r.x], 1);
        atomicAdd(&g_cnt[r.y], 1);
        atomicAdd(&g_cnt[r.z], 1);
        atomicAdd(&g_cnt[r.w], 1);
    } else {
        for (int i = base; i < n_edges; i++)
            atomicAdd(&g_cnt[__ldg(erow + i)], 1);
    }
}

__global__ __launch_bounds__(1024)
void scan1_kernel() {
    __shared__ int sdata[1024];
    const int t = threadIdx.x;
    const int i = blockIdx.x * 1024 + t;
    int c = (i < N_NODES) ? g_cnt[i] : 0;
    sdata[t] = c;
    __syncthreads();
    #pragma unroll
    for (int off = 1; off < 1024; off <<= 1) {
        int v = (t >= off) ? sdata[t - off] : 0;
        __syncthreads();
        sdata[t] += v;
        __syncthreads();
    }
    if (i < N_NODES) g_ofs[i] = sdata[t] - c;
    if (t == 1023) g_bsum[blockIdx.x] = sdata[1023];
}

__global__ __launch_bounds__(256)
void scan2_kernel() {
    __shared__ int sdata[256];
    const int t = threadIdx.x;
    int c = (t < SCAN_BLOCKS) ? g_bsum[t] : 0;
    sdata[t] = c;
    __syncthreads();
    #pragma unroll
    for (int off = 1; off < 256; off <<= 1) {
        int v = (t >= off) ? sdata[t - off] : 0;
        __syncthreads();
        sdata[t] += v;
        __syncthreads();
    }
    if (t < SCAN_BLOCKS) g_boff[t] = sdata[t] - c;
    if (t == SCAN_BLOCKS - 1) g_ofs[N_NODES] = sdata[t];
}

__global__ __launch_bounds__(1024)
void scan3_kernel() {
    const int i = blockIdx.x * 1024 + threadIdx.x;
    if (i < N_NODES) {
        int v = g_ofs[i] + g_boff[blockIdx.x];
        g_ofs[i] = v;
        g_cur[i] = v;
    }
}

// Scatter: 8 edges/thread; rows cached from the load phase (no reload in the
// atomic phase); atomics phase-split from stores.
__global__ void scatter_kernel(const int*   __restrict__ erow,
                               const int*   __restrict__ ecol,
                               const float* __restrict__ eval,
                               int n_edges) {
    int base = (blockIdx.x * blockDim.x + threadIdx.x) * 8;
    int  pos[8], c[8], r[8];
    float v[8];
    #pragma unroll
    for (int j = 0; j < 8; j++) {
        int i = base + j;
        if (i < n_edges) {
            r[j] = __ldg(erow + i);
            c[j] = __ldg(ecol + i);
            v[j] = __ldg(eval + i);
        }
    }
    #pragma unroll
    for (int j = 0; j < 8; j++) {
        int i = base + j;
        if (i < n_edges)
            pos[j] = atomicAdd(&g_cur[r[j]], 1);
    }
    #pragma unroll
    for (int j = 0; j < 8; j++) {
        int i = base + j;
        if (i < n_edges)
            g_edges[pos[j]] = make_int2(c[j], __float_as_int(v[j]));
    }
}

// ---------------------------------------------------------------------------
// Text GEMM on tensor cores (verified round 13): fp16 m16n8k16, fp32 accum,
// prep-folded epilogue writing interleaved fp16 b0.
// ---------------------------------------------------------------------------
#define ASTRIDE 24
#define BSTRIDE 72
#define CSTRIDE 68
#define A_BUF_BYTES (128 * ASTRIDE * 2)
#define B_BUF_BYTES (16 * BSTRIDE * 2)
#define C_BYTES     (128 * CSTRIDE * 4)

__global__ __launch_bounds__(256)
void gemm_text_mma(const float* __restrict__ A,
                   const float* __restrict__ W,
                   const float* __restrict__ bias,
                   const float* __restrict__ uemb,
                   const float* __restrict__ iemb) {
    __shared__ __align__(16) char smem_raw[C_BYTES];
    __half* As[2] = { (__half*)smem_raw,
                      (__half*)(smem_raw + A_BUF_BYTES) };
    __half* Bs[2] = { (__half*)(smem_raw + 2 * A_BUF_BYTES),
                      (__half*)(smem_raw + 2 * A_BUF_BYTES + B_BUF_BYTES) };
    float*  Csm   = (float*)smem_raw;

    const int tid  = threadIdx.x;
    const int m0   = blockIdx.x * 128;
    const int wid  = tid >> 5;
    const int lane = tid & 31;

    float d[8][4];
    #pragma unroll
    for (int j = 0; j < 8; j++)
        #pragma unroll
        for (int q = 0; q < 4; q++) d[j][q] = 0.f;

    auto load_tile = [&](int k0, int s) {
        #pragma unroll
        for (int p = 0; p < 2; p++) {
            int idx = tid + p * 256;
            int m   = idx >> 2;
            int kq  = idx & 3;
            float4 a4 = make_float4(0.f, 0.f, 0.f, 0.f);
            int gm = m0 + m;
            if (gm < N_NODES)
                a4 = *(const float4*)(A + (size_t)gm * TEXT_DIM + k0 + kq * 4);
            *(__half2*)&As[s][m * ASTRIDE + kq * 4]     = __floats2half2_rn(a4.x, a4.y);
            *(__half2*)&As[s][m * ASTRIDE + kq * 4 + 2] = __floats2half2_rn(a4.z, a4.w);
        }
        {
            int k  = tid >> 4;
            int nq = tid & 15;
            float4 b4 = *(const float4*)(W + (size_t)(k0 + k) * 64 + nq * 4);
            *(__half2*)&Bs[s][k * BSTRIDE + nq * 4]     = __floats2half2_rn(b4.x, b4.y);
            *(__half2*)&Bs[s][k * BSTRIDE + nq * 4 + 2] = __floats2half2_rn(b4.z, b4.w);
        }
    };

    load_tile(0, 0);
    __syncthreads();

    const int NK = TEXT_DIM / 16;   // 24
    for (int it = 0; it < NK; it++) {
        int s = it & 1;
        if (it + 1 < NK) load_tile((it + 1) * 16, s ^ 1);

        uint32_t a0, a1, a2, a3;
        {
            const __half* p = &As[s][(wid * 16 + (lane & 15)) * ASTRIDE +
                                     ((lane >> 4) << 3)];
            uint32_t addr = (uint32_t)__cvta_generic_to_shared(p);
            asm volatile(
                "ldmatrix.sync.aligned.m8n8.x4.shared.b16 {%0,%1,%2,%3}, [%4];"
                : "=r"(a0), "=r"(a1), "=r"(a2), "=r"(a3) : "r"(addr));
        }
        #pragma unroll
        for (int nb = 0; nb < 4; nb++) {
            uint32_t b0, b1, b2, b3;
            const __half* p = &Bs[s][(lane & 15) * BSTRIDE + nb * 16 +
                                     ((lane >> 4) << 3)];
            uint32_t addr = (uint32_t)__cvta_generic_to_shared(p);
            asm volatile(
                "ldmatrix.sync.aligned.m8n8.x4.trans.shared.b16 {%0,%1,%2,%3}, [%4];"
                : "=r"(b0), "=r"(b1), "=r"(b2), "=r"(b3) : "r"(addr));
            asm volatile(
                "mma.sync.aligned.m16n8k16.row.col.f32.f16.f16.f32 "
                "{%0,%1,%2,%3}, {%4,%5,%6,%7}, {%8,%9}, {%0,%1,%2,%3};"
                : "+f"(d[2 * nb][0]), "+f"(d[2 * nb][1]),
                  "+f"(d[2 * nb][2]), "+f"(d[2 * nb][3])
                : "r"(a0), "r"(a1), "r"(a2), "r"(a3), "r"(b0), "r"(b1));
            asm volatile(
                "mma.sync.aligned.m16n8k16.row.col.f32.f16.f16.f32 "
                "{%0,%1,%2,%3}, {%4,%5,%6,%7}, {%8,%9}, {%0,%1,%2,%3};"
                : "+f"(d[2 * nb + 1][0]), "+f"(d[2 * nb + 1][1]),
                  "+f"(d[2 * nb + 1][2]), "+f"(d[2 * nb + 1][3])
                : "r"(a0), "r"(a1), "r"(a2), "r"(a3), "r"(b2), "r"(b3));
        }
        __syncthreads();
    }

    {
        int r0 = wid * 16 + (lane >> 2);
        int c0 = (lane & 3) * 2;
        #pragma unroll
        for (int j = 0; j < 8; j++) {
            *(float2*)&Csm[r0 * CSTRIDE + j * 8 + c0] =
                make_float2(d[j][0], d[j][1]);
            *(float2*)&Csm[(r0 + 8) * CSTRIDE + j * 8 + c0] =
                make_float2(d[j][2], d[j][3]);
        }
    }
    __syncthreads();

    const int tr = tid >> 4;
    const int tc = tid & 15;
    float4 bv = *(const float4*)(bias + tc * 4);
    #pragma unroll
    for (int i = 0; i < 8; i++) {
        int m  = tr * 8 + i;
        int gm = m0 + m;
        if (gm < N_NODES) {
            float4 o = *(float4*)&Csm[m * CSTRIDE + tc * 4];
            o.x += bv.x; o.y += bv.y; o.z += bv.z; o.w += bv.w;
            const float4* idp = (gm < NUM_USERS)
                ? (const float4*)(uemb + (size_t)gm * 64)
                : (const float4*)(iemb + (size_t)(gm - NUM_USERS) * 64);
            float4 idv = __ldg(idp + tc);
            uint4 w;
            w.x = pack_h2(idv.x, idv.y);
            w.y = pack_h2(o.x, o.y);
            w.z = pack_h2(idv.z, idv.w);
            w.w = pack_h2(o.z, o.w);
            ((uint4*)g_b0)[(size_t)gm * 16 + tc] = w;
        }
    }
}

// ---------------------------------------------------------------------------
// CSR SpMM v4: 16 edges/iter (8 per half-warp), pipelined descriptors,
// LDG.128 gathers serving both streams, shfl combine, fp16 out.
// ---------------------------------------------------------------------------
#define SPMM_FMA(W, V)                                                        \
    do {                                                                      \
        float2 _f;                                                            \
        _f = unpack_h2((W).x); aid0.x += _f.x * (V); aid0.y += _f.y * (V);    \
        _f = unpack_h2((W).y); atx0.x += _f.x * (V); atx0.y += _f.y * (V);    \
        _f = unpack_h2((W).z); aid1.x += _f.x * (V); aid1.y += _f.y * (V);    \
        _f = unpack_h2((W).w); atx1.x += _f.x * (V); atx1.y += _f.y * (V);    \
    } while (0)

__global__ void spmm_csr_kernel(const unsigned* __restrict__ src_b,
                                unsigned* __restrict__ dst_b) {
    int row  = (blockIdx.x * blockDim.x + threadIdx.x) >> 5;
    int lane = threadIdx.x & 31;
    if (row >= N_NODES) return;

    const int h = lane >> 4;
    const int l = lane & 15;

    int beg = __ldg(&g_ofs[row]);
    int end = __ldg(&g_ofs[row + 1]);
    int cnt = end - beg;
    int nfull = cnt >> 4;          // iterations of 16 edges (8 per half-warp)

    const uint4* src = (const uint4*)src_b;

    float2 aid0 = make_float2(0.f, 0.f), atx0 = make_float2(0.f, 0.f);
    float2 aid1 = make_float2(0.f, 0.f), atx1 = make_float2(0.f, 0.f);

    int e = beg + h;
    int2 d0, d1, d2, d3, d4, d5, d6, d7;
    if (nfull > 0) {
        d0 = __ldg(&g_edges[e]);
        d1 = __ldg(&g_edges[e + 2]);
        d2 = __ldg(&g_edges[e + 4]);
        d3 = __ldg(&g_edges[e + 6]);
        d4 = __ldg(&g_edges[e + 8]);
        d5 = __ldg(&g_edges[e + 10]);
        d6 = __ldg(&g_edges[e + 12]);
        d7 = __ldg(&g_edges[e + 14]);
    }
    for (int it = 0; it < nfull; it++) {
        uint4 w0 = __ldg(src + (size_t)d0.x * 16 + l);
        uint4 w1 = __ldg(src + (size_t)d1.x * 16 + l);
        uint4 w2 = __ldg(src + (size_t)d2.x * 16 + l);
        uint4 w3 = __ldg(src + (size_t)d3.x * 16 + l);
        uint4 w4 = __ldg(src + (size_t)d4.x * 16 + l);
        uint4 w5 = __ldg(src + (size_t)d5.x * 16 + l);
        uint4 w6 = __ldg(src + (size_t)d6.x * 16 + l);
        uint4 w7 = __ldg(src + (size_t)d7.x * 16 + l);
        float v0 = __int_as_float(d0.y);
        float v1 = __int_as_float(d1.y);
        float v2 = __int_as_float(d2.y);
        float v3 = __int_as_float(d3.y);
        float v4 = __int_as_float(d4.y);
        float v5 = __int_as_float(d5.y);
        float v6 = __int_as_float(d6.y);
        float v7 = __int_as_float(d7.y);
        e += 16;
        if (it + 1 < nfull) {
            d0 = __ldg(&g_edges[e]);
            d1 = __ldg(&g_edges[e + 2]);
            d2 = __ldg(&g_edges[e + 4]);
            d3 = __ldg(&g_edges[e + 6]);
            d4 = __ldg(&g_edges[e + 8]);
            d5 = __ldg(&g_edges[e + 10]);
            d6 = __ldg(&g_edges[e + 12]);
            d7 = __ldg(&g_edges[e + 14]);
        }
        SPMM_FMA(w0, v0);
        SPMM_FMA(w1, v1);
        SPMM_FMA(w2, v2);
        SPMM_FMA(w3, v3);
        SPMM_FMA(w4, v4);
        SPMM_FMA(w5, v5);
        SPMM_FMA(w6, v6);
        SPMM_FMA(w7, v7);
    }
    while (e < end) {              // tail, <= 15 edges total
        int2 d = __ldg(&g_edges[e]);
        uint4 w = __ldg(src + (size_t)d.x * 16 + l);
        float v = __int_as_float(d.y);
        SPMM_FMA(w, v);
        e += 2;
    }

    aid0.x += __shfl_xor_sync(0xffffffffu, aid0.x, 16);
    aid0.y += __shfl_xor_sync(0xffffffffu, aid0.y, 16);
    atx0.x += __shfl_xor_sync(0xffffffffu, atx0.x, 16);
    atx0.y += __shfl_xor_sync(0xffffffffu, atx0.y, 16);
    aid1.x += __shfl_xor_sync(0xffffffffu, aid1.x, 16);
    aid1.y += __shfl_xor_sync(0xffffffffu, aid1.y, 16);
    atx1.x += __shfl_xor_sync(0xffffffffu, atx1.x, 16);
    atx1.y += __shfl_xor_sync(0xffffffffu, atx1.y, 16);

    if (h == 0) {
        uint4 w;
        w.x = pack_h2(aid0.x, aid0.y);
        w.y = pack_h2(atx0.x, atx0.y);
        w.z = pack_h2(aid1.x, aid1.y);
        w.w = pack_h2(atx1.x, atx1.y);
        ((uint4*)dst_b)[(size_t)row * 16 + l] = w;
    }
}

// ---------------------------------------------------------------------------
// Fusion GEMM + gate epilogue (unchanged). Inputs all fp16: b0, b1, b2.
// ---------------------------------------------------------------------------
#define FUSE_SMEM (128 * 132 * 4 + 128 * 64 * 4)
__global__ __launch_bounds__(256)
void fuse_gemm_kernel(const int*   __restrict__ tail_mask,
                      const float* __restrict__ W_fuse,
                      const float* __restrict__ b_fuse,
                      const float* __restrict__ tail_amp,
                      float* __restrict__ out) {
    extern __shared__ float sm[];
    float* As = sm;
    float* Bs = sm + 128 * 132;

    const int tid = threadIdx.x;
    const int m0  = blockIdx.x * 128;

    #pragma unroll
    for (int p = 0; p < 8; p++) {
        int i = tid + p * 256;
        ((float4*)Bs)[i] = ((const float4*)W_fuse)[i];
    }

    const float amp = 1.f + 1.f / (1.f + __expf(-tail_amp[0]));

    {
        int n    = tid >> 1;
        int node = m0 + n;
        int sub  = tid & 1;
        bool valid = node < N_NODES;
        int nc = valid ? node : 0;
        const uint4* b0p = (const uint4*)g_b0 + (size_t)nc * 16;
        const uint4* b1p = (const uint4*)g_b1 + (size_t)nc * 16;
        const uint4* b2p = (const uint4*)g_b2 + (size_t)nc * 16;
        const float third = 1.f / 3.f;
        float tmul = (valid && __ldg(tail_mask + nc) != 0) ? amp * third : third;
        #pragma unroll 4
        for (int q = sub * 8; q < sub * 8 + 8; q++) {
            uint4 w0 = valid ? __ldg(b0p + q) : make_uint4(0u, 0u, 0u, 0u);
            uint4 w1 = valid ? __ldg(b1p + q) : make_uint4(0u, 0u, 0u, 0u);
            uint4 w2 = valid ? __ldg(b2p + q) : make_uint4(0u, 0u, 0u, 0u);
            float2 i0a = unpack_h2(w0.x), t0a = unpack_h2(w0.y);
            float2 i0b = unpack_h2(w0.z), t0b = unpack_h2(w0.w);
            float2 i1a = unpack_h2(w1.x), t1a = unpack_h2(w1.y);
            float2 i1b = unpack_h2(w1.z), t1b = unpack_h2(w1.w);
            float2 i2a = unpack_h2(w2.x), t2a = unpack_h2(w2.y);
            float2 i2b = unpack_h2(w2.z), t2b = unpack_h2(w2.w);
            int d = 4 * q;
            As[(d + 0) * 132 + n]      = (i0a.x + i1a.x + i2a.x) * third;
            As[(d + 1) * 132 + n]      = (i0a.y + i1a.y + i2a.y) * third;
            As[(d + 2) * 132 + n]      = (i0b.x + i1b.x + i2b.x) * third;
            As[(d + 3) * 132 + n]      = (i0b.y + i1b.y + i2b.y) * third;
            As[(64 + d + 0) * 132 + n] = (t0a.x + t1a.x + t2a.x) * tmul;
            As[(64 + d + 1) * 132 + n] = (t0a.y + t1a.y + t2a.y) * tmul;
            As[(64 + d + 2) * 132 + n] = (t0b.x + t1b.x + t2b.x) * tmul;
            As[(64 + d + 3) * 132 + n] = (t0b.y + t1b.y + t2b.y) * tmul;
        }
    }
    __syncthreads();

    const int tr = tid >> 4;
    const int tc = tid & 15;

    unsigned long long acc2[4][4];
    #pragma unroll
    for (int ip = 0; ip < 4; ip++)
        #pragma unroll
        for (int j = 0; j < 4; j++) acc2[ip][j] = 0ull;

    #pragma unroll 4
    for (int k = 0; k < 128; k++) {
        const unsigned long long* pa =
            (const unsigned long long*)(As + k * 132 + tr * 8);
        unsigned long long av[4] = {pa[0], pa[1], pa[2], pa[3]};
        float4 b = *(const float4*)(Bs + k * 64 + tc * 4);
        unsigned long long bd[4];
        asm("mov.b64 %0, {%1, %1};" : "=l"(bd[0]) : "r"(__float_as_uint(b.x)));
        asm("mov.b64 %0, {%1, %1};" : "=l"(bd[1]) : "r"(__float_as_uint(b.y)));
        asm("mov.b64 %0, {%1, %1};" : "=l"(bd[2]) : "r"(__float_as_uint(b.z)));
        asm("mov.b64 %0, {%1, %1};" : "=l"(bd[3]) : "r"(__float_as_uint(b.w)));
        #pragma unroll
        for (int ip = 0; ip < 4; ip++)
            #pragma unroll
            for (int j = 0; j < 4; j++)
                asm("fma.rn.f32x2 %0, %1, %2, %3;"
                    : "=l"(acc2[ip][j])
                    : "l"(av[ip]), "l"(bd[j]), "l"(acc2[ip][j]));
    }

    float4 bv = *(const float4*)(b_fuse + tc * 4);
    #pragma unroll
    for (int ip = 0; ip < 4; ip++) {
        float2 lo_hi[4];
        #pragma unroll
        for (int j = 0; j < 4; j++)
            lo_hi[j] = *reinterpret_cast<float2*>(&acc2[ip][j]);
        #pragma unroll
        for (int half = 0; half < 2; half++) {
            int m  = tr * 8 + 2 * ip + half;
            int gm = m0 + m;
            if (gm < N_NODES) {
                float4 o;
                float accs[4] = {
                    (half ? lo_hi[0].y : lo_hi[0].x) + bv.x,
                    (half ? lo_hi[1].y : lo_hi[1].x) + bv.y,
                    (half ? lo_hi[2].y : lo_hi[2].x) + bv.z,
                    (half ? lo_hi[3].y : lo_hi[3].x) + bv.w };
                float* po = (float*)&o;
                #pragma unroll
                for (int j = 0; j < 4; j++) {
                    int d = tc * 4 + j;
                    float gate = 1.f / (1.f + __expf(-accs[j]));
                    float idf = As[d * 132 + m];
                    float tf  = As[(64 + d) * 132 + m];
                    po[j] = gate * idf + (1.f - gate) * tf;
                }
                *(float4*)(out + (size_t)gm * 64 + tc * 4) = o;
            }
        }
    }
}

// ---------------------------------------------------------------------------
// Launch: side stream runs the self-contained CSR chain; main runs the
// tensor-core GEMM. Join, propagate, fuse.
// ---------------------------------------------------------------------------
extern "C" void kernel_launch(void* const* d_in, const int* in_sizes, int n_in,
                              void* d_out, int out_size) {
    const float* text_feats = (const float*)d_in[0];
    const int*   edge_row   = (const int*)d_in[1];
    const int*   edge_col   = (const int*)d_in[2];
    const float* edge_val   = (const float*)d_in[3];
    const int*   tail_mask  = (const int*)d_in[4];
    const float* user_emb   = (const float*)d_in[5];
    const float* item_emb   = (const float*)d_in[6];
    const float* W_text     = (const float*)d_in[7];
    const float* b_text     = (const float*)d_in[8];
    const float* W_fuse     = (const float*)d_in[9];
    const float* b_fuse     = (const float*)d_in[10];
    const float* tail_amp   = (const float*)d_in[11];
    float*       out        = (float*)d_out;

    const int n_edges = in_sizes[1];

    unsigned *p_b0, *p_b1, *p_b2;
    int* p_cnt;
    cudaGetSymbolAddress((void**)&p_b0, g_b0);
    cudaGetSymbolAddress((void**)&p_b1, g_b1);
    cudaGetSymbolAddress((void**)&p_b2, g_b2);
    cudaGetSymbolAddress((void**)&p_cnt, g_cnt);

    static cudaStream_t s_side = nullptr;
    static cudaEvent_t  ev_fork = nullptr, ev_side = nullptr;
    if (s_side == nullptr) {
        cudaStreamCreateWithFlags(&s_side, cudaStreamNonBlocking);
        cudaEventCreateWithFlags(&ev_fork, cudaEventDisableTiming);
        cudaEventCreateWithFlags(&ev_side, cudaEventDisableTiming);
        cudaFuncSetAttribute(fuse_gemm_kernel,
                             cudaFuncAttributeMaxDynamicSharedMemorySize,
                             FUSE_SMEM);
    }

    // Fork: self-contained CSR build on the side stream
    cudaEventRecord(ev_fork, 0);
    cudaStreamWaitEvent(s_side, ev_fork, 0);
    cudaMemsetAsync(p_cnt, 0, N_NODES * sizeof(int), s_side);
    {
        int threads_needed = (n_edges + 3) / 4;
        hist_kernel<<<(threads_needed + 255) / 256, 256, 0, s_side>>>(
            edge_row, n_edges);
    }
    scan1_kernel<<<SCAN_BLOCKS, 1024, 0, s_side>>>();
    scan2_kernel<<<1, 256, 0, s_side>>>();
    scan3_kernel<<<SCAN_BLOCKS, 1024, 0, s_side>>>();
    {
        int threads_needed = (n_edges + 7) / 8;
        scatter_kernel<<<(threads_needed + 255) / 256, 256, 0, s_side>>>(
            edge_row, edge_col, edge_val, n_edges);
    }
    cudaEventRecord(ev_side, s_side);

    // Main stream: tensor-core GEMM (writes full b0)
    gemm_text_mma<<<(N_NODES + 127) / 128, 256>>>(text_feats, W_text, b_text,
                                                  user_emb, item_emb);

    // Join, then propagate
    cudaStreamWaitEvent(0, ev_side, 0);
    {
        int blocks = (N_NODES * 32 + 255) / 256;
        spmm_csr_kernel<<<blocks, 256>>>(p_b0, p_b1);
        spmm_csr_kernel<<<blocks, 256>>>(p_b1, p_b2);
    }
    // Fusion epilogue
    fuse_gemm_kernel<<<(N_NODES + 127) / 128, 256, FUSE_SMEM>>>(
        tail_mask, W_fuse, b_fuse, tail_amp, out);
}

// round 16
// speedup vs baseline: 1.0482x; 1.0482x over previous
#include <cuda_runtime.h>
#include <cuda_bf16.h>
#include <cuda_fp16.h>
#include <cstdint>

#define NUM_USERS 100000
#define NUM_ITEMS 50000
#define N_NODES   150000
#define EMB_DIM   64
#define TEXT_DIM  384
#define N64 (N_NODES * EMB_DIM)
#define MAX_EDGES 5000000
#define SCAN_BLOCKS 147           // 147 * 1024 = 150528 >= N_NODES

// fp16 interleaved buffers: per node 16 uint4; uint4 q of a node =
//   (id pair 2q, tx pair 2q, id pair 2q+1, tx pair 2q+1)
__device__ unsigned g_b0[N_NODES * 64];
__device__ unsigned g_b1[N_NODES * 64];
__device__ unsigned g_b2[N_NODES * 64];

// CSR machinery
__device__ int  g_cnt[N_NODES];
__device__ int  g_ofs[N_NODES + 1];
__device__ int  g_cur[N_NODES];
__device__ int  g_bsum[SCAN_BLOCKS];
__device__ int  g_boff[SCAN_BLOCKS];
__device__ int2 g_edges[MAX_EDGES];   // (col, val bits), row-sorted

static __device__ __forceinline__ unsigned pack_h2(float a, float b) {
    __half2 h = __floats2half2_rn(a, b);
    return *reinterpret_cast<unsigned*>(&h);
}
static __device__ __forceinline__ float2 unpack_h2(unsigned w) {
    return __half22float2(*reinterpret_cast<__half2*>(&w));
}

// ---------------------------------------------------------------------------
// CSR build (side stream): memset zero, int4 histogram, 3-phase scan, scatter
// ---------------------------------------------------------------------------
__global__ void hist_kernel(const int* __restrict__ erow, int n_edges) {
    int base = (blockIdx.x * blockDim.x + threadIdx.x) * 4;
    if (base + 3 < n_edges) {
        int4 r = *(const int4*)(erow + base);
        atomicAdd(&g_cnt[r.x], 1);
        atomicAdd(&g_cnt[r.y], 1);
        atomicAdd(&g_cnt[r.z], 1);
        atomicAdd(&g_cnt[r.w], 1);
    } else {
        for (int i = base; i < n_edges; i++)
            atomicAdd(&g_cnt[__ldg(erow + i)], 1);
    }
}

__global__ __launch_bounds__(1024)
void scan1_kernel() {
    __shared__ int sdata[1024];
    const int t = threadIdx.x;
    const int i = blockIdx.x * 1024 + t;
    int c = (i < N_NODES) ? g_cnt[i] : 0;
    sdata[t] = c;
    __syncthreads();
    #pragma unroll
    for (int off = 1; off < 1024; off <<= 1) {
        int v = (t >= off) ? sdata[t - off] : 0;
        __syncthreads();
        sdata[t] += v;
        __syncthreads();
    }
    if (i < N_NODES) g_ofs[i] = sdata[t] - c;
    if (t == 1023) g_bsum[blockIdx.x] = sdata[1023];
}

__global__ __launch_bounds__(256)
void scan2_kernel() {
    __shared__ int sdata[256];
    const int t = threadIdx.x;
    int c = (t < SCAN_BLOCKS) ? g_bsum[t] : 0;
    sdata[t] = c;
    __syncthreads();
    #pragma unroll
    for (int off = 1; off < 256; off <<= 1) {
        int v = (t >= off) ? sdata[t - off] : 0;
        __syncthreads();
        sdata[t] += v;
        __syncthreads();
    }
    if (t < SCAN_BLOCKS) g_boff[t] = sdata[t] - c;
    if (t == SCAN_BLOCKS - 1) g_ofs[N_NODES] = sdata[t];
}

__global__ __launch_bounds__(1024)
void scan3_kernel() {
    const int i = blockIdx.x * 1024 + threadIdx.x;
    if (i < N_NODES) {
        int v = g_ofs[i] + g_boff[blockIdx.x];
        g_ofs[i] = v;
        g_cur[i] = v;
    }
}

// Scatter: 8 edges/thread; rows cached from the load phase; atomics
// phase-split from stores.
__global__ void scatter_kernel(const int*   __restrict__ erow,
                               const int*   __restrict__ ecol,
                               const float* __restrict__ eval,
                               int n_edges) {
    int base = (blockIdx.x * blockDim.x + threadIdx.x) * 8;
    int  pos[8], c[8], r[8];
    float v[8];
    #pragma unroll
    for (int j = 0; j < 8; j++) {
        int i = base + j;
        if (i < n_edges) {
            r[j] = __ldg(erow + i);
            c[j] = __ldg(ecol + i);
            v[j] = __ldg(eval + i);
        }
    }
    #pragma unroll
    for (int j = 0; j < 8; j++) {
        int i = base + j;
        if (i < n_edges)
            pos[j] = atomicAdd(&g_cur[r[j]], 1);
    }
    #pragma unroll
    for (int j = 0; j < 8; j++) {
        int i = base + j;
        if (i < n_edges)
            g_edges[pos[j]] = make_int2(c[j], __float_as_int(v[j]));
    }
}

// ---------------------------------------------------------------------------
// Text GEMM on tensor cores (verified round 13): fp16 m16n8k16, fp32 accum,
// prep-folded epilogue writing interleaved fp16 b0.
// ---------------------------------------------------------------------------
#define ASTRIDE 24
#define BSTRIDE 72
#define CSTRIDE 68
#define A_BUF_BYTES (128 * ASTRIDE * 2)
#define B_BUF_BYTES (16 * BSTRIDE * 2)
#define C_BYTES     (128 * CSTRIDE * 4)

__global__ __launch_bounds__(256)
void gemm_text_mma(const float* __restrict__ A,
                   const float* __restrict__ W,
                   const float* __restrict__ bias,
                   const float* __restrict__ uemb,
                   const float* __restrict__ iemb) {
    __shared__ __align__(16) char smem_raw[C_BYTES];
    __half* As[2] = { (__half*)smem_raw,
                      (__half*)(smem_raw + A_BUF_BYTES) };
    __half* Bs[2] = { (__half*)(smem_raw + 2 * A_BUF_BYTES),
                      (__half*)(smem_raw + 2 * A_BUF_BYTES + B_BUF_BYTES) };
    float*  Csm   = (float*)smem_raw;

    const int tid  = threadIdx.x;
    const int m0   = blockIdx.x * 128;
    const int wid  = tid >> 5;
    const int lane = tid & 31;

    float d[8][4];
    #pragma unroll
    for (int j = 0; j < 8; j++)
        #pragma unroll
        for (int q = 0; q < 4; q++) d[j][q] = 0.f;

    auto load_tile = [&](int k0, int s) {
        #pragma unroll
        for (int p = 0; p < 2; p++) {
            int idx = tid + p * 256;
            int m   = idx >> 2;
            int kq  = idx & 3;
            float4 a4 = make_float4(0.f, 0.f, 0.f, 0.f);
            int gm = m0 + m;
            if (gm < N_NODES)
                a4 = *(const float4*)(A + (size_t)gm * TEXT_DIM + k0 + kq * 4);
            *(__half2*)&As[s][m * ASTRIDE + kq * 4]     = __floats2half2_rn(a4.x, a4.y);
            *(__half2*)&As[s][m * ASTRIDE + kq * 4 + 2] = __floats2half2_rn(a4.z, a4.w);
        }
        {
            int k  = tid >> 4;
            int nq = tid & 15;
            float4 b4 = *(const float4*)(W + (size_t)(k0 + k) * 64 + nq * 4);
            *(__half2*)&Bs[s][k * BSTRIDE + nq * 4]     = __floats2half2_rn(b4.x, b4.y);
            *(__half2*)&Bs[s][k * BSTRIDE + nq * 4 + 2] = __floats2half2_rn(b4.z, b4.w);
        }
    };

    load_tile(0, 0);
    __syncthreads();

    const int NK = TEXT_DIM / 16;   // 24
    for (int it = 0; it < NK; it++) {
        int s = it & 1;
        if (it + 1 < NK) load_tile((it + 1) * 16, s ^ 1);

        uint32_t a0, a1, a2, a3;
        {
            const __half* p = &As[s][(wid * 16 + (lane & 15)) * ASTRIDE +
                                     ((lane >> 4) << 3)];
            uint32_t addr = (uint32_t)__cvta_generic_to_shared(p);
            asm volatile(
                "ldmatrix.sync.aligned.m8n8.x4.shared.b16 {%0,%1,%2,%3}, [%4];"
                : "=r"(a0), "=r"(a1), "=r"(a2), "=r"(a3) : "r"(addr));
        }
        #pragma unroll
        for (int nb = 0; nb < 4; nb++) {
            uint32_t b0, b1, b2, b3;
            const __half* p = &Bs[s][(lane & 15) * BSTRIDE + nb * 16 +
                                     ((lane >> 4) << 3)];
            uint32_t addr = (uint32_t)__cvta_generic_to_shared(p);
            asm volatile(
                "ldmatrix.sync.aligned.m8n8.x4.trans.shared.b16 {%0,%1,%2,%3}, [%4];"
                : "=r"(b0), "=r"(b1), "=r"(b2), "=r"(b3) : "r"(addr));
            asm volatile(
                "mma.sync.aligned.m16n8k16.row.col.f32.f16.f16.f32 "
                "{%0,%1,%2,%3}, {%4,%5,%6,%7}, {%8,%9}, {%0,%1,%2,%3};"
                : "+f"(d[2 * nb][0]), "+f"(d[2 * nb][1]),
                  "+f"(d[2 * nb][2]), "+f"(d[2 * nb][3])
                : "r"(a0), "r"(a1), "r"(a2), "r"(a3), "r"(b0), "r"(b1));
            asm volatile(
                "mma.sync.aligned.m16n8k16.row.col.f32.f16.f16.f32 "
                "{%0,%1,%2,%3}, {%4,%5,%6,%7}, {%8,%9}, {%0,%1,%2,%3};"
                : "+f"(d[2 * nb + 1][0]), "+f"(d[2 * nb + 1][1]),
                  "+f"(d[2 * nb + 1][2]), "+f"(d[2 * nb + 1][3])
                : "r"(a0), "r"(a1), "r"(a2), "r"(a3), "r"(b2), "r"(b3));
        }
        __syncthreads();
    }

    {
        int r0 = wid * 16 + (lane >> 2);
        int c0 = (lane & 3) * 2;
        #pragma unroll
        for (int j = 0; j < 8; j++) {
            *(float2*)&Csm[r0 * CSTRIDE + j * 8 + c0] =
                make_float2(d[j][0], d[j][1]);
            *(float2*)&Csm[(r0 + 8) * CSTRIDE + j * 8 + c0] =
                make_float2(d[j][2], d[j][3]);
        }
    }
    __syncthreads();

    const int tr = tid >> 4;
    const int tc = tid & 15;
    float4 bv = *(const float4*)(bias + tc * 4);
    #pragma unroll
    for (int i = 0; i < 8; i++) {
        int m  = tr * 8 + i;
        int gm = m0 + m;
        if (gm < N_NODES) {
            float4 o = *(float4*)&Csm[m * CSTRIDE + tc * 4];
            o.x += bv.x; o.y += bv.y; o.z += bv.z; o.w += bv.w;
            const float4* idp = (gm < NUM_USERS)
                ? (const float4*)(uemb + (size_t)gm * 64)
                : (const float4*)(iemb + (size_t)(gm - NUM_USERS) * 64);
            float4 idv = __ldg(idp + tc);
            uint4 w;
            w.x = pack_h2(idv.x, idv.y);
            w.y = pack_h2(o.x, o.y);
            w.z = pack_h2(idv.z, idv.w);
            w.w = pack_h2(o.z, o.w);
            ((uint4*)g_b0)[(size_t)gm * 16 + tc] = w;
        }
    }
}

// ---------------------------------------------------------------------------
// CSR SpMM v3 (round-14 verified optimum): 12 edges/iter (6 per half-warp),
// pipelined descriptors, LDG.128 gathers serving both streams, shfl combine.
// ---------------------------------------------------------------------------
#define SPMM_FMA(W, V)                                                        \
    do {                                                                      \
        float2 _f;                                                            \
        _f = unpack_h2((W).x); aid0.x += _f.x * (V); aid0.y += _f.y * (V);    \
        _f = unpack_h2((W).y); atx0.x += _f.x * (V); atx0.y += _f.y * (V);    \
        _f = unpack_h2((W).z); aid1.x += _f.x * (V); aid1.y += _f.y * (V);    \
        _f = unpack_h2((W).w); atx1.x += _f.x * (V); atx1.y += _f.y * (V);    \
    } while (0)

__global__ void spmm_csr_kernel(const unsigned* __restrict__ src_b,
                                unsigned* __restrict__ dst_b) {
    int row  = (blockIdx.x * blockDim.x + threadIdx.x) >> 5;
    int lane = threadIdx.x & 31;
    if (row >= N_NODES) return;

    const int h = lane >> 4;
    const int l = lane & 15;

    int beg = __ldg(&g_ofs[row]);
    int end = __ldg(&g_ofs[row + 1]);
    int cnt = end - beg;
    int nfull = cnt / 12;          // iterations of 12 edges (6 per half-warp)

    const uint4* src = (const uint4*)src_b;

    float2 aid0 = make_float2(0.f, 0.f), atx0 = make_float2(0.f, 0.f);
    float2 aid1 = make_float2(0.f, 0.f), atx1 = make_float2(0.f, 0.f);

    int e = beg + h;
    int2 d0, d1, d2, d3, d4, d5;
    if (nfull > 0) {
        d0 = __ldg(&g_edges[e]);
        d1 = __ldg(&g_edges[e + 2]);
        d2 = __ldg(&g_edges[e + 4]);
        d3 = __ldg(&g_edges[e + 6]);
        d4 = __ldg(&g_edges[e + 8]);
        d5 = __ldg(&g_edges[e + 10]);
    }
    for (int it = 0; it < nfull; it++) {
        uint4 w0 = __ldg(src + (size_t)d0.x * 16 + l);
        uint4 w1 = __ldg(src + (size_t)d1.x * 16 + l);
        uint4 w2 = __ldg(src + (size_t)d2.x * 16 + l);
        uint4 w3 = __ldg(src + (size_t)d3.x * 16 + l);
        uint4 w4 = __ldg(src + (size_t)d4.x * 16 + l);
        uint4 w5 = __ldg(src + (size_t)d5.x * 16 + l);
        float v0 = __int_as_float(d0.y);
        float v1 = __int_as_float(d1.y);
        float v2 = __int_as_float(d2.y);
        float v3 = __int_as_float(d3.y);
        float v4 = __int_as_float(d4.y);
        float v5 = __int_as_float(d5.y);
        e += 12;
        if (it + 1 < nfull) {
            d0 = __ldg(&g_edges[e]);
            d1 = __ldg(&g_edges[e + 2]);
            d2 = __ldg(&g_edges[e + 4]);
            d3 = __ldg(&g_edges[e + 6]);
            d4 = __ldg(&g_edges[e + 8]);
            d5 = __ldg(&g_edges[e + 10]);
        }
        SPMM_FMA(w0, v0);
        SPMM_FMA(w1, v1);
        SPMM_FMA(w2, v2);
        SPMM_FMA(w3, v3);
        SPMM_FMA(w4, v4);
        SPMM_FMA(w5, v5);
    }
    while (e < end) {              // tail, <= 11 edges total
        int2 d = __ldg(&g_edges[e]);
        uint4 w = __ldg(src + (size_t)d.x * 16 + l);
        float v = __int_as_float(d.y);
        SPMM_FMA(w, v);
        e += 2;
    }

    aid0.x += __shfl_xor_sync(0xffffffffu, aid0.x, 16);
    aid0.y += __shfl_xor_sync(0xffffffffu, aid0.y, 16);
    atx0.x += __shfl_xor_sync(0xffffffffu, atx0.x, 16);
    atx0.y += __shfl_xor_sync(0xffffffffu, atx0.y, 16);
    aid1.x += __shfl_xor_sync(0xffffffffu, aid1.x, 16);
    aid1.y += __shfl_xor_sync(0xffffffffu, aid1.y, 16);
    atx1.x += __shfl_xor_sync(0xffffffffu, atx1.x, 16);
    atx1.y += __shfl_xor_sync(0xffffffffu, atx1.y, 16);

    if (h == 0) {
        uint4 w;
        w.x = pack_h2(aid0.x, aid0.y);
        w.y = pack_h2(atx0.x, atx0.y);
        w.z = pack_h2(aid1.x, aid1.y);
        w.w = pack_h2(atx1.x, atx1.y);
        ((uint4*)dst_b)[(size_t)row * 16 + l] = w;
    }
}

// ---------------------------------------------------------------------------
// Fusion GEMM + gate epilogue (unchanged). Inputs all fp16: b0, b1, b2.
// ---------------------------------------------------------------------------
#define FUSE_SMEM (128 * 132 * 4 + 128 * 64 * 4)
__global__ __launch_bounds__(256)
void fuse_gemm_kernel(const int*   __restrict__ tail_mask,
                      const float* __restrict__ W_fuse,
                      const float* __restrict__ b_fuse,
                      const float* __restrict__ tail_amp,
                      float* __restrict__ out) {
    extern __shared__ float sm[];
    float* As = sm;
    float* Bs = sm + 128 * 132;

    const int tid = threadIdx.x;
    const int m0  = blockIdx.x * 128;

    #pragma unroll
    for (int p = 0; p < 8; p++) {
        int i = tid + p * 256;
        ((float4*)Bs)[i] = ((const float4*)W_fuse)[i];
    }

    const float amp = 1.f + 1.f / (1.f + __expf(-tail_amp[0]));

    {
        int n    = tid >> 1;
        int node = m0 + n;
        int sub  = tid & 1;
        bool valid = node < N_NODES;
        int nc = valid ? node : 0;
        const uint4* b0p = (const uint4*)g_b0 + (size_t)nc * 16;
        const uint4* b1p = (const uint4*)g_b1 + (size_t)nc * 16;
        const uint4* b2p = (const uint4*)g_b2 + (size_t)nc * 16;
        const float third = 1.f / 3.f;
        float tmul = (valid && __ldg(tail_mask + nc) != 0) ? amp * third : third;
        #pragma unroll 4
        for (int q = sub * 8; q < sub * 8 + 8; q++) {
            uint4 w0 = valid ? __ldg(b0p + q) : make_uint4(0u, 0u, 0u, 0u);
            uint4 w1 = valid ? __ldg(b1p + q) : make_uint4(0u, 0u, 0u, 0u);
            uint4 w2 = valid ? __ldg(b2p + q) : make_uint4(0u, 0u, 0u, 0u);
            float2 i0a = unpack_h2(w0.x), t0a = unpack_h2(w0.y);
            float2 i0b = unpack_h2(w0.z), t0b = unpack_h2(w0.w);
            float2 i1a = unpack_h2(w1.x), t1a = unpack_h2(w1.y);
            float2 i1b = unpack_h2(w1.z), t1b = unpack_h2(w1.w);
            float2 i2a = unpack_h2(w2.x), t2a = unpack_h2(w2.y);
            float2 i2b = unpack_h2(w2.z), t2b = unpack_h2(w2.w);
            int d = 4 * q;
            As[(d + 0) * 132 + n]      = (i0a.x + i1a.x + i2a.x) * third;
            As[(d + 1) * 132 + n]      = (i0a.y + i1a.y + i2a.y) * third;
            As[(d + 2) * 132 + n]      = (i0b.x + i1b.x + i2b.x) * third;
            As[(d + 3) * 132 + n]      = (i0b.y + i1b.y + i2b.y) * third;
            As[(64 + d + 0) * 132 + n] = (t0a.x + t1a.x + t2a.x) * tmul;
            As[(64 + d + 1) * 132 + n] = (t0a.y + t1a.y + t2a.y) * tmul;
            As[(64 + d + 2) * 132 + n] = (t0b.x + t1b.x + t2b.x) * tmul;
            As[(64 + d + 3) * 132 + n] = (t0b.y + t1b.y + t2b.y) * tmul;
        }
    }
    __syncthreads();

    const int tr = tid >> 4;
    const int tc = tid & 15;

    unsigned long long acc2[4][4];
    #pragma unroll
    for (int ip = 0; ip < 4; ip++)
        #pragma unroll
        for (int j = 0; j < 4; j++) acc2[ip][j] = 0ull;

    #pragma unroll 4
    for (int k = 0; k < 128; k++) {
        const unsigned long long* pa =
            (const unsigned long long*)(As + k * 132 + tr * 8);
        unsigned long long av[4] = {pa[0], pa[1], pa[2], pa[3]};
        float4 b = *(const float4*)(Bs + k * 64 + tc * 4);
        unsigned long long bd[4];
        asm("mov.b64 %0, {%1, %1};" : "=l"(bd[0]) : "r"(__float_as_uint(b.x)));
        asm("mov.b64 %0, {%1, %1};" : "=l"(bd[1]) : "r"(__float_as_uint(b.y)));
        asm("mov.b64 %0, {%1, %1};" : "=l"(bd[2]) : "r"(__float_as_uint(b.z)));
        asm("mov.b64 %0, {%1, %1};" : "=l"(bd[3]) : "r"(__float_as_uint(b.w)));
        #pragma unroll
        for (int ip = 0; ip < 4; ip++)
            #pragma unroll
            for (int j = 0; j < 4; j++)
                asm("fma.rn.f32x2 %0, %1, %2, %3;"
                    : "=l"(acc2[ip][j])
                    : "l"(av[ip]), "l"(bd[j]), "l"(acc2[ip][j]));
    }

    float4 bv = *(const float4*)(b_fuse + tc * 4);
    #pragma unroll
    for (int ip = 0; ip < 4; ip++) {
        float2 lo_hi[4];
        #pragma unroll
        for (int j = 0; j < 4; j++)
            lo_hi[j] = *reinterpret_cast<float2*>(&acc2[ip][j]);
        #pragma unroll
        for (int half = 0; half < 2; half++) {
            int m  = tr * 8 + 2 * ip + half;
            int gm = m0 + m;
            if (gm < N_NODES) {
                float4 o;
                float accs[4] = {
                    (half ? lo_hi[0].y : lo_hi[0].x) + bv.x,
                    (half ? lo_hi[1].y : lo_hi[1].x) + bv.y,
                    (half ? lo_hi[2].y : lo_hi[2].x) + bv.z,
                    (half ? lo_hi[3].y : lo_hi[3].x) + bv.w };
                float* po = (float*)&o;
                #pragma unroll
                for (int j = 0; j < 4; j++) {
                    int d = tc * 4 + j;
                    float gate = 1.f / (1.f + __expf(-accs[j]));
                    float idf = As[d * 132 + m];
                    float tf  = As[(64 + d) * 132 + m];
                    po[j] = gate * idf + (1.f - gate) * tf;
                }
                *(float4*)(out + (size_t)gm * 64 + tc * 4) = o;
            }
        }
    }
}

// ---------------------------------------------------------------------------
// Launch: side stream runs the self-contained CSR chain; main runs the
// tensor-core GEMM. Join, propagate, fuse.
// ---------------------------------------------------------------------------
extern "C" void kernel_launch(void* const* d_in, const int* in_sizes, int n_in,
                              void* d_out, int out_size) {
    const float* text_feats = (const float*)d_in[0];
    const int*   edge_row   = (const int*)d_in[1];
    const int*   edge_col   = (const int*)d_in[2];
    const float* edge_val   = (const float*)d_in[3];
    const int*   tail_mask  = (const int*)d_in[4];
    const float* user_emb   = (const float*)d_in[5];
    const float* item_emb   = (const float*)d_in[6];
    const float* W_text     = (const float*)d_in[7];
    const float* b_text     = (const float*)d_in[8];
    const float* W_fuse     = (const float*)d_in[9];
    const float* b_fuse     = (const float*)d_in[10];
    const float* tail_amp   = (const float*)d_in[11];
    float*       out        = (float*)d_out;

    const int n_edges = in_sizes[1];

    unsigned *p_b0, *p_b1, *p_b2;
    int* p_cnt;
    cudaGetSymbolAddress((void**)&p_b0, g_b0);
    cudaGetSymbolAddress((void**)&p_b1, g_b1);
    cudaGetSymbolAddress((void**)&p_b2, g_b2);
    cudaGetSymbolAddress((void**)&p_cnt, g_cnt);

    static cudaStream_t s_side = nullptr;
    static cudaEvent_t  ev_fork = nullptr, ev_side = nullptr;
    if (s_side == nullptr) {
        cudaStreamCreateWithFlags(&s_side, cudaStreamNonBlocking);
        cudaEventCreateWithFlags(&ev_fork, cudaEventDisableTiming);
        cudaEventCreateWithFlags(&ev_side, cudaEventDisableTiming);
        cudaFuncSetAttribute(fuse_gemm_kernel,
                             cudaFuncAttributeMaxDynamicSharedMemorySize,
                             FUSE_SMEM);
    }

    // Fork: self-contained CSR build on the side stream
    cudaEventRecord(ev_fork, 0);
    cudaStreamWaitEvent(s_side, ev_fork, 0);
    cudaMemsetAsync(p_cnt, 0, N_NODES * sizeof(int), s_side);
    {
        int threads_needed = (n_edges + 3) / 4;
        hist_kernel<<<(threads_needed + 255) / 256, 256, 0, s_side>>>(
            edge_row, n_edges);
    }
    scan1_kernel<<<SCAN_BLOCKS, 1024, 0, s_side>>>();
    scan2_kernel<<<1, 256, 0, s_side>>>();
    scan3_kernel<<<SCAN_BLOCKS, 1024, 0, s_side>>>();
    {
        int threads_needed = (n_edges + 7) / 8;
        scatter_kernel<<<(threads_needed + 255) / 256, 256, 0, s_side>>>(
            edge_row, edge_col, edge_val, n_edges);
    }
    cudaEventRecord(ev_side, s_side);

    // Main stream: tensor-core GEMM (writes full b0)
    gemm_text_mma<<<(N_NODES + 127) / 128, 256>>>(text_feats, W_text, b_text,
                                                  user_emb, item_emb);

    // Join, then propagate
    cudaStreamWaitEvent(0, ev_side, 0);
    {
        int blocks = (N_NODES * 32 + 255) / 256;
        spmm_csr_kernel<<<blocks, 256>>>(p_b0, p_b1);
        spmm_csr_kernel<<<blocks, 256>>>(p_b1, p_b2);
    }
    // Fusion epilogue
    fuse_gemm_kernel<<<(N_NODES + 127) / 128, 256, FUSE_SMEM>>>(
        tail_mask, W_fuse, b_fuse, tail_amp, out);
}